// round 3
// baseline (speedup 1.0000x reference)
#include <cuda_runtime.h>
#include <cstdint>

#define Hh 128
#define Gg 512
#define SEQ 12
#define TB 32
#define NTHREADS 256

// ---------------- scratch: transposed / fused weights ----------------
__device__ float g_WtI[132 * 512];   // W_init^T, padded K rows
__device__ float g_Wt0[132 * 512];   // W_ih_l0^T, padded
__device__ float g_Wth0[128 * 512];  // W_hh_l0^T
__device__ float g_Wt1[256 * 512];   // [W_ih_l1 ; W_hh_l1]^T  (K=256)
__device__ float g_bsum0[512];
__device__ float g_bsum1[512];

__global__ void prep_kernel(const float* __restrict__ Wi, const float* __restrict__ W0,
                            const float* __restrict__ Wh0,
                            const float* __restrict__ W1i, const float* __restrict__ W1h,
                            const float* __restrict__ bi0, const float* __restrict__ bh0,
                            const float* __restrict__ bi1, const float* __restrict__ bh1) {
    int stride = gridDim.x * blockDim.x;
    int t0 = blockIdx.x * blockDim.x + threadIdx.x;
    for (int i = t0; i < 132 * 512; i += stride) {
        int kk = i >> 9, j = i & 511;
        g_WtI[i] = (kk < 129) ? Wi[j * 129 + kk] : 0.f;
        g_Wt0[i] = (kk < 129) ? W0[j * 129 + kk] : 0.f;
    }
    for (int i = t0; i < 128 * 512; i += stride) {
        int kk = i >> 9, j = i & 511;
        g_Wth0[i] = Wh0[j * 128 + kk];
    }
    for (int i = t0; i < 256 * 512; i += stride) {
        int kk = i >> 9, j = i & 511;
        g_Wt1[i] = (kk < 128) ? W1i[j * 128 + kk] : W1h[j * 128 + (kk - 128)];
    }
    for (int i = t0; i < 512; i += stride) {
        g_bsum0[i] = bi0[i] + bh0[i];
        g_bsum1[i] = bi1[i] + bh1[i];
    }
}

// ---------------- packed f32x2 helpers ----------------
typedef unsigned long long u64;

__device__ __forceinline__ u64 pk2(float lo, float hi) {
    u64 r; asm("mov.b64 %0, {%1, %2};" : "=l"(r) : "f"(lo), "f"(hi)); return r;
}
__device__ __forceinline__ void upk2(u64 v, float& lo, float& hi) {
    asm("mov.b64 {%0, %1}, %2;" : "=f"(lo), "=f"(hi) : "l"(v));
}
__device__ __forceinline__ u64 dup2(float x) { return pk2(x, x); }
__device__ __forceinline__ void fma2(u64& d, u64 a, u64 b) {
    asm("fma.rn.f32x2 %0, %1, %2, %0;" : "+l"(d) : "l"(a), "l"(b));
}

__device__ __forceinline__ float sigm(float x) {
    return __fdividef(1.f, 1.f + __expf(-x));
}
__device__ __forceinline__ float tanh_(float x) {
    x = fmaxf(x, -44.f);                 // keep __expf finite
    float e = __expf(-2.f * x);
    return __fdividef(1.f - e, 1.f + e);
}

// GEMM micro-tile: 4 batches (2 packed pairs) x 4 gate columns, K-loop.
// wt: [K][512] transposed weights in global/L2.  shA: [K][RS] shared, batch-major rows.
template <int K, int RS>
__device__ __forceinline__ void gemm_tile(const float* __restrict__ wt,
                                          const float* shA, int rowbase,
                                          int chunk, int jq, u64 acc[2][4]) {
    const float4* wp = reinterpret_cast<const float4*>(wt) + (chunk * 32 + jq);
#pragma unroll 8
    for (int kk = 0; kk < K; ++kk) {
        float4 w4 = __ldg(wp + kk * 128);              // 512 floats = 128 float4 per row
        const float* a = shA + kk * RS + rowbase;
        u64 h0 = *reinterpret_cast<const u64*>(a);     // batches b0,b1
        u64 h1 = *reinterpret_cast<const u64*>(a + 2); // batches b2,b3
        u64 w0 = dup2(w4.x), w1 = dup2(w4.y), w2 = dup2(w4.z), w3 = dup2(w4.w);
        fma2(acc[0][0], h0, w0); fma2(acc[1][0], h1, w0);
        fma2(acc[0][1], h0, w1); fma2(acc[1][1], h1, w1);
        fma2(acc[0][2], h0, w2); fma2(acc[1][2], h1, w2);
        fma2(acc[0][3], h0, w3); fma2(acc[1][3], h1, w3);
    }
}

// elementwise LSTM gate update for layer l (0/1)
__device__ __forceinline__ void ewphase(int l, int tid, float* sh_g, float* sh_c, float* sh_hT) {
    int b = tid & 31;
    int k0 = (tid >> 5) << 4;
    float* cb = sh_c + l * 4096;
    int hoff = l << 7;
#pragma unroll
    for (int i = 0; i < 16; ++i) {
        int k = k0 + i;
        float gi = sh_g[k * 33 + b];
        float gf = sh_g[(128 + k) * 33 + b];
        float gg = sh_g[(256 + k) * 33 + b];
        float go = sh_g[(384 + k) * 33 + b];
        float c  = cb[k * 32 + b];
        float cn = sigm(gf) * c + sigm(gi) * tanh_(gg);
        float hn = sigm(go) * tanh_(cn);
        cb[k * 32 + b] = cn;
        sh_hT[(hoff + k) * 32 + b] = hn;
    }
}

#define SMEM_FLOATS (2 * 512 * 33 + 256 * 32 + 2 * 128 * 32)
#define SMEM_BYTES (SMEM_FLOATS * 4)

__global__ void __launch_bounds__(NTHREADS, 1)
traj_kernel(const float* __restrict__ ff, const float* __restrict__ ip,
            const float* __restrict__ b_init,
            const float* __restrict__ W_out, const float* __restrict__ b_out,
            float* __restrict__ out, int B) {
    extern __shared__ float sm[];
    float* sh_pre0 = sm;                     // [512][33]
    float* sh_g    = sm + 512 * 33;          // [512][33]
    float* sh_hT   = sm + 2 * 512 * 33;      // [256][32]  rows 0..127=h1, 128..255=h2
    float* sh_c    = sh_hT + 256 * 32;       // [2][128][32]
    float* sh_xT   = sh_g;                   // overlay [132][64] during phase 0

    const int tid  = threadIdx.x;
    const int base = blockIdx.x * TB;
    const int bq   = tid >> 5;               // 0..7  (batch quad; constant per warp)
    const int jq   = tid & 31;                // 0..31 (gate quad within chunk)

    // ---- phase 0a: stage x rows (32 tile rows + 2x16 init rows), transposed ----
    for (int i = tid; i < 64 * 132; i += NTHREADS) {
        int row = i / 132, kk = i - row * 132;
        int gb;
        if (row < 32)      gb = base + row;
        else if (row < 48) gb = (base >> 1) + (row - 32);
        else               gb = (B >> 1) + (base >> 1) + (row - 48);
        float v = 0.f;
        if (kk < 128)       v = ff[(size_t)gb * 128 + kk];
        else if (kk == 128) v = ip[gb];
        sh_xT[kk * 64 + row] = v;
    }
    __syncthreads();

    // ---- phase 0b: pre0 = x @ W_ih_l0^T + (b_ih_l0+b_hh_l0), stored [j][b] ----
    for (int chunk = 0; chunk < 4; ++chunk) {
        u64 acc[2][4];
#pragma unroll
        for (int ji = 0; ji < 4; ++ji) {
            float bz = g_bsum0[chunk * 128 + 4 * jq + ji];
            acc[0][ji] = dup2(bz); acc[1][ji] = dup2(bz);
        }
        gemm_tile<129, 64>(g_Wt0, sh_xT, 4 * bq, chunk, jq, acc);
#pragma unroll
        for (int ji = 0; ji < 4; ++ji) {
            int j = chunk * 128 + 4 * jq + ji;
            float v0, v1, v2, v3;
            upk2(acc[0][ji], v0, v1); upk2(acc[1][ji], v2, v3);
            sh_pre0[j * 33 + 4 * bq + 0] = v0;
            sh_pre0[j * 33 + 4 * bq + 1] = v1;
            sh_pre0[j * 33 + 4 * bq + 2] = v2;
            sh_pre0[j * 33 + 4 * bq + 3] = v3;
        }
    }

    // ---- phase 0c: init states (torch-faithful reshape shuffle) ----
    // half 0: rows base/2+i -> layer0 states of batches 2i,2i+1
    // half 1: rows B/2+base/2+i -> layer1 states
    {
        int half = tid >> 7;                  // 0/1, 128 threads each
        int t2   = tid & 127;
        int bq2  = t2 >> 5;                   // 0..3 -> 16 init rows
        int jq2  = t2 & 31;
        int rowbase = 32 + half * 16 + 4 * bq2;
        for (int chunk = 0; chunk < 4; ++chunk) {
            u64 acc[2][4];
#pragma unroll
            for (int ji = 0; ji < 4; ++ji) {
                float bz = b_init[chunk * 128 + 4 * jq2 + ji];
                acc[0][ji] = dup2(bz); acc[1][ji] = dup2(bz);
            }
            gemm_tile<129, 64>(g_WtI, sh_xT, rowbase, chunk, jq2, acc);
#pragma unroll
            for (int ji = 0; ji < 4; ++ji) {
                float v[4];
                upk2(acc[0][ji], v[0], v[1]); upk2(acc[1][ji], v[2], v[3]);
                int k = 4 * jq2 + ji;
#pragma unroll
                for (int bi = 0; bi < 4; ++bi) {
                    int iloc = 4 * bq2 + bi;
                    int bl   = 2 * iloc + (chunk & 1);   // local batch
                    if (chunk < 2) sh_hT[(half * 128 + k) * 32 + bl] = v[bi];
                    else           sh_c[half * 4096 + k * 32 + bl]   = v[bi];
                }
            }
        }
    }
    __syncthreads();

    // ---- main recurrence ----
    for (int t = 0; t < SEQ; ++t) {
        // GEMM0: g = pre0 + h1 @ W_hh_l0^T   (K=128)
        for (int chunk = 0; chunk < 4; ++chunk) {
            u64 acc[2][4];
#pragma unroll
            for (int ji = 0; ji < 4; ++ji) {
                int j = chunk * 128 + 4 * jq + ji;
                acc[0][ji] = pk2(sh_pre0[j * 33 + 4 * bq + 0], sh_pre0[j * 33 + 4 * bq + 1]);
                acc[1][ji] = pk2(sh_pre0[j * 33 + 4 * bq + 2], sh_pre0[j * 33 + 4 * bq + 3]);
            }
            gemm_tile<128, 32>(g_Wth0, sh_hT, 4 * bq, chunk, jq, acc);
#pragma unroll
            for (int ji = 0; ji < 4; ++ji) {
                int j = chunk * 128 + 4 * jq + ji;
                float v0, v1, v2, v3;
                upk2(acc[0][ji], v0, v1); upk2(acc[1][ji], v2, v3);
                sh_g[j * 33 + 4 * bq + 0] = v0;
                sh_g[j * 33 + 4 * bq + 1] = v1;
                sh_g[j * 33 + 4 * bq + 2] = v2;
                sh_g[j * 33 + 4 * bq + 3] = v3;
            }
        }
        __syncthreads();
        ewphase(0, tid, sh_g, sh_c, sh_hT);    // updates c1, h1 (hT rows 0..127)
        __syncthreads();

        // GEMM1: g = bsum1 + h1@W_ih_l1^T + h2@W_hh_l1^T  (fused K=256)
        for (int chunk = 0; chunk < 4; ++chunk) {
            u64 acc[2][4];
#pragma unroll
            for (int ji = 0; ji < 4; ++ji) {
                float bz = g_bsum1[chunk * 128 + 4 * jq + ji];
                acc[0][ji] = dup2(bz); acc[1][ji] = dup2(bz);
            }
            gemm_tile<256, 32>(g_Wt1, sh_hT, 4 * bq, chunk, jq, acc);
#pragma unroll
            for (int ji = 0; ji < 4; ++ji) {
                int j = chunk * 128 + 4 * jq + ji;
                float v0, v1, v2, v3;
                upk2(acc[0][ji], v0, v1); upk2(acc[1][ji], v2, v3);
                sh_g[j * 33 + 4 * bq + 0] = v0;
                sh_g[j * 33 + 4 * bq + 1] = v1;
                sh_g[j * 33 + 4 * bq + 2] = v2;
                sh_g[j * 33 + 4 * bq + 3] = v3;
            }
        }
        __syncthreads();
        ewphase(1, tid, sh_g, sh_c, sh_hT);    // updates c2, h2 (hT rows 128..255)
        __syncthreads();

        // output head: out[b, t, :] = h2 @ W_out^T + b_out
        if (tid < 64) {
            int b = tid >> 1, o = tid & 1;
            float s = b_out[o];
            const float* w = W_out + o * 128;
#pragma unroll 8
            for (int k = 0; k < 128; ++k)
                s += sh_hT[(128 + k) * 32 + b] * __ldg(&w[k]);
            out[(size_t)(base + b) * (SEQ * 2) + t * 2 + o] = s;
        }
        // no extra sync needed: next writes to regions the head touches are
        // separated by >=2 __syncthreads in the following iteration.
    }
}

extern "C" void kernel_launch(void* const* d_in, const int* in_sizes, int n_in,
                              void* d_out, int out_size) {
    const float* ff   = (const float*)d_in[0];   // fused_features [B,128]
    const float* ip   = (const float*)d_in[1];   // intent_prob    [B,1]
    const float* Wi   = (const float*)d_in[2];   // W_init  [512,129]
    const float* bi   = (const float*)d_in[3];   // b_init  [512]
    const float* W0   = (const float*)d_in[4];   // W_ih_l0 [512,129]
    const float* Wh0  = (const float*)d_in[5];   // W_hh_l0 [512,128]
    const float* bi0  = (const float*)d_in[6];
    const float* bh0  = (const float*)d_in[7];
    const float* W1i  = (const float*)d_in[8];   // W_ih_l1 [512,128]
    const float* W1h  = (const float*)d_in[9];   // W_hh_l1 [512,128]
    const float* bi1  = (const float*)d_in[10];
    const float* bh1  = (const float*)d_in[11];
    const float* Wout = (const float*)d_in[12];  // [2,128]
    const float* bout = (const float*)d_in[13];  // [2]
    (void)n_in; (void)out_size;

    int B = in_sizes[0] / 128;

    prep_kernel<<<128, 256>>>(Wi, W0, Wh0, W1i, W1h, bi0, bh0, bi1, bh1);

    cudaFuncSetAttribute(traj_kernel, cudaFuncAttributeMaxDynamicSharedMemorySize, SMEM_BYTES);
    traj_kernel<<<B / TB, NTHREADS, SMEM_BYTES>>>(ff, ip, bi, Wout, bout, (float*)d_out, B);
}

// round 6
// speedup vs baseline: 1.3397x; 1.3397x over previous
#include <cuda_runtime.h>
#include <cstdint>

#define Hh 128
#define SEQ 12
#define TB 32
#define NTHREADS 512

// ---------------- scratch: transposed / fused weights ----------------
__device__ float g_WtI[132 * 512];   // W_init^T, K padded to 132
__device__ float g_Wt0[132 * 512];   // W_ih_l0^T, padded
__device__ float g_Wth0[128 * 512];  // W_hh_l0^T
__device__ float g_Wt1[256 * 512];   // [W_ih_l1 ; W_hh_l1]^T  (K=256)
__device__ float g_bsum0[512];
__device__ float g_bsum1[512];

__global__ void prep_kernel(const float* __restrict__ Wi, const float* __restrict__ W0,
                            const float* __restrict__ Wh0,
                            const float* __restrict__ W1i, const float* __restrict__ W1h,
                            const float* __restrict__ bi0, const float* __restrict__ bh0,
                            const float* __restrict__ bi1, const float* __restrict__ bh1) {
    int stride = gridDim.x * blockDim.x;
    int t0 = blockIdx.x * blockDim.x + threadIdx.x;
    for (int i = t0; i < 132 * 512; i += stride) {
        int kk = i >> 9, j = i & 511;
        g_WtI[i] = (kk < 129) ? Wi[j * 129 + kk] : 0.f;
        g_Wt0[i] = (kk < 129) ? W0[j * 129 + kk] : 0.f;
    }
    for (int i = t0; i < 128 * 512; i += stride) {
        int kk = i >> 9, j = i & 511;
        g_Wth0[i] = Wh0[j * 128 + kk];
    }
    for (int i = t0; i < 256 * 512; i += stride) {
        int kk = i >> 9, j = i & 511;
        g_Wt1[i] = (kk < 128) ? W1i[j * 128 + kk] : W1h[j * 128 + (kk - 128)];
    }
    for (int i = t0; i < 512; i += stride) {
        g_bsum0[i] = bi0[i] + bh0[i];
        g_bsum1[i] = bi1[i] + bh1[i];
    }
}

// ---------------- packed f32x2 helpers ----------------
typedef unsigned long long u64;

__device__ __forceinline__ u64 pk2(float lo, float hi) {
    u64 r; asm("mov.b64 %0, {%1, %2};" : "=l"(r) : "f"(lo), "f"(hi)); return r;
}
__device__ __forceinline__ void upk2(u64 v, float& lo, float& hi) {
    asm("mov.b64 {%0, %1}, %2;" : "=f"(lo), "=f"(hi) : "l"(v));
}
__device__ __forceinline__ u64 dup2(float x) { return pk2(x, x); }
__device__ __forceinline__ void fma2(u64& d, u64 a, u64 b) {
    asm("fma.rn.f32x2 %0, %1, %2, %0;" : "+l"(d) : "l"(a), "l"(b));
}

__device__ __forceinline__ float sigm(float x) {
    return __fdividef(1.f, 1.f + __expf(-x));
}
__device__ __forceinline__ float tanh_(float x) {
    x = fmaxf(x, -44.f);
    float e = __expf(-2.f * x);
    return __fdividef(1.f - e, 1.f + e);
}

// GEMM micro-tile: 4 batches x 8 columns per thread, K-loop.
// wt: [K][512] weights (L2-resident). sa: [K][RS] shared, h values DUPLICATED
// (each value stored twice, so a 64-bit broadcast LDS yields a packed operand).
// Columns per thread: {4cg..4cg+3} and {256+4cg..256+4cg+3} as packed pairs.
template <int K, int RS>
__device__ __forceinline__ void gemm512(const float* __restrict__ wt,
                                        const float* sa, int rowoff, int cg,
                                        u64 acc[4][4]) {
    const ulonglong2* wp = reinterpret_cast<const ulonglong2*>(wt);
#pragma unroll 4
    for (int k = 0; k < K; ++k) {
        ulonglong2 wl = __ldg(wp + k * 128 + cg);        // cols 4cg..4cg+3
        ulonglong2 wh = __ldg(wp + k * 128 + 64 + cg);   // cols 256+4cg..+3
        const float* a = sa + k * RS + rowoff;
        u64 h0 = *reinterpret_cast<const u64*>(a);       // (h,h) batch 0
        u64 h1 = *reinterpret_cast<const u64*>(a + 2);
        u64 h2 = *reinterpret_cast<const u64*>(a + 4);
        u64 h3 = *reinterpret_cast<const u64*>(a + 6);
        fma2(acc[0][0], h0, wl.x); fma2(acc[0][1], h0, wl.y);
        fma2(acc[0][2], h0, wh.x); fma2(acc[0][3], h0, wh.y);
        fma2(acc[1][0], h1, wl.x); fma2(acc[1][1], h1, wl.y);
        fma2(acc[1][2], h1, wh.x); fma2(acc[1][3], h1, wh.y);
        fma2(acc[2][0], h2, wl.x); fma2(acc[2][1], h2, wl.y);
        fma2(acc[2][2], h2, wh.x); fma2(acc[2][3], h2, wh.y);
        fma2(acc[3][0], h3, wl.x); fma2(acc[3][1], h3, wl.y);
        fma2(acc[3][2], h3, wh.x); fma2(acc[3][3], h3, wh.y);
    }
}

__device__ __forceinline__ void bias_init(const float* __restrict__ bias, int cg,
                                          u64 acc[4][4]) {
    ulonglong2 bl = __ldg(reinterpret_cast<const ulonglong2*>(bias) + cg);
    ulonglong2 bh = __ldg(reinterpret_cast<const ulonglong2*>(bias) + 64 + cg);
#pragma unroll
    for (int bi = 0; bi < 4; ++bi) {
        acc[bi][0] = bl.x; acc[bi][1] = bl.y;
        acc[bi][2] = bh.x; acc[bi][3] = bh.y;
    }
}

__device__ __forceinline__ void store_g(float* sh_g, const u64 acc[4][4],
                                        int bg, int cg) {
#pragma unroll
    for (int bi = 0; bi < 4; ++bi) {
        int b = 4 * bg + bi;
#pragma unroll
        for (int cp = 0; cp < 4; ++cp) {
            int j0 = (cp < 2) ? (4 * cg + 2 * cp) : (256 + 4 * cg + 2 * (cp - 2));
            float v0, v1; upk2(acc[bi][cp], v0, v1);
            sh_g[j0 * 33 + b] = v0;
            sh_g[(j0 + 1) * 33 + b] = v1;
        }
    }
}

// elementwise LSTM update, layer l. 512 threads cover 128k x 32b.
__device__ __forceinline__ void ewphase(int l, int tid, float* sh_g,
                                        float* sh_c, float* sh_hd) {
    int b = tid & 31;
    int k0 = (tid >> 5) << 3;          // 8 k's per thread
    float* cb = sh_c + l * 4096;
    int hoff = l << 7;
#pragma unroll
    for (int i = 0; i < 8; ++i) {
        int k = k0 + i;
        float gi = sh_g[k * 33 + b];
        float gf = sh_g[(128 + k) * 33 + b];
        float gg = sh_g[(256 + k) * 33 + b];
        float go = sh_g[(384 + k) * 33 + b];
        float c  = cb[k * 32 + b];
        float cn = sigm(gf) * c + sigm(gi) * tanh_(gg);
        float hn = sigm(go) * tanh_(cn);
        cb[k * 32 + b] = cn;
        *reinterpret_cast<u64*>(&sh_hd[(hoff + k) * 64 + 2 * b]) = dup2(hn);
    }
}

// smem: sh_g [512][33] (67584B, overlaid by x-staging [132][128] = same size),
//       sh_hd [256][64] dup'd h (65536B), sh_c [2][128][32] (32768B)
#define SMEM_FLOATS (512 * 33 + 256 * 64 + 2 * 128 * 32)
#define SMEM_BYTES (SMEM_FLOATS * 4)

__global__ void __launch_bounds__(NTHREADS, 1)
traj_kernel(const float* __restrict__ ff, const float* __restrict__ ip,
            const float* __restrict__ b_init,
            const float* __restrict__ W_out, const float* __restrict__ b_out,
            float* __restrict__ out, int B) {
    extern __shared__ float sm[];
    float* sh_g  = sm;                        // [512][33]
    float* sh_hd = sm + 512 * 33;             // [256][64] rows 0..127=h1 dup, 128..255=h2 dup
    float* sh_c  = sh_hd + 256 * 64;          // [2][128][32]
    float* sh_xd = sh_g;                      // overlay [132][128] during phase 0 (dup'd)

    const int tid  = threadIdx.x;
    const int base = blockIdx.x * TB;
    const int bg   = tid >> 6;                // 0..7, constant per warp-pair
    const int cg   = tid & 63;                // 0..63 column group

    // ---- phase 0a: stage x rows (32 tile + 16 l0-init + 16 l1-init), dup'd ----
    for (int i = tid; i < 64 * 132; i += NTHREADS) {
        int row = i / 132, kk = i - row * 132;
        int gb;
        if (row < 32)      gb = base + row;
        else if (row < 48) gb = (base >> 1) + (row - 32);
        else               gb = (B >> 1) + (base >> 1) + (row - 48);
        float v = 0.f;
        if (kk < 128)       v = ff[(size_t)gb * 128 + kk];
        else if (kk == 128) v = ip[gb];
        sh_xd[kk * 128 + 2 * row]     = v;
        sh_xd[kk * 128 + 2 * row + 1] = v;
    }
    __syncthreads();

    // ---- phase 0b: pre0 = x @ W_ih_l0^T + bsum0 (kept in REGISTERS) ----
    u64 pre0[4][4];
    bias_init(g_bsum0, cg, pre0);
    gemm512<132, 128>(g_Wt0, sh_xd, 8 * bg, cg, pre0);

    // ---- phase 0c: init states via W_init (torch reshape(2,B,H) shuffle) ----
    {
        u64 acc2[4][4];
        bias_init(b_init, cg, acc2);
        gemm512<132, 128>(g_WtI, sh_xd, 64 + 8 * bg, cg, acc2);
        // scatter: init row rl (0..31): rl<16 -> layer0 source row i=rl,
        // rl>=16 -> layer1 row i=rl-16. col j: sect=j>>7: 0,1 -> h (batch 2i+sect),
        // 2,3 -> c (batch 2i+sect-2); k=j&127.
        __syncthreads();   // all sh_xd reads done before overwriting sh_g region? (disjoint targets, but keep ordering cheap)
#pragma unroll
        for (int bi = 0; bi < 4; ++bi) {
            int rl = 4 * bg + bi;
            int half = rl >> 4;
            int ii = rl & 15;
#pragma unroll
            for (int cp = 0; cp < 4; ++cp) {
                int j0 = (cp < 2) ? (4 * cg + 2 * cp) : (256 + 4 * cg + 2 * (cp - 2));
                float v0, v1; upk2(acc2[bi][cp], v0, v1);
#pragma unroll
                for (int e = 0; e < 2; ++e) {
                    int j = j0 + e;
                    float v = e ? v1 : v0;
                    int k = j & 127;
                    int sect = j >> 7;
                    if (sect < 2) {
                        int bl = 2 * ii + sect;
                        u64* p = reinterpret_cast<u64*>(&sh_hd[(half * 128 + k) * 64 + 2 * bl]);
                        *p = dup2(v);
                    } else {
                        int bl = 2 * ii + (sect - 2);
                        sh_c[half * 4096 + k * 32 + bl] = v;
                    }
                }
            }
        }
    }
    __syncthreads();

    // ---- main recurrence ----
    for (int t = 0; t < SEQ; ++t) {
        // GEMM0: g = pre0 + h1 @ W_hh_l0^T   (K=128)
        {
            u64 acc[4][4];
#pragma unroll
            for (int bi = 0; bi < 4; ++bi)
#pragma unroll
                for (int cp = 0; cp < 4; ++cp) acc[bi][cp] = pre0[bi][cp];
            gemm512<128, 64>(g_Wth0, sh_hd, 8 * bg, cg, acc);
            store_g(sh_g, acc, bg, cg);
        }
        __syncthreads();
        ewphase(0, tid, sh_g, sh_c, sh_hd);     // updates c1, h1 (hd rows 0..127)
        __syncthreads();

        // GEMM1: g = bsum1 + [h1;h2] @ [W_ih_l1;W_hh_l1]^T  (fused K=256)
        {
            u64 acc[4][4];
            bias_init(g_bsum1, cg, acc);
            gemm512<256, 64>(g_Wt1, sh_hd, 8 * bg, cg, acc);
            store_g(sh_g, acc, bg, cg);
        }
        __syncthreads();
        ewphase(1, tid, sh_g, sh_c, sh_hd);     // updates c2, h2 (hd rows 128..255)
        __syncthreads();

        // output head: out[b, t, :] = h2 @ W_out^T + b_out
        if (tid < 64) {
            int b = tid >> 1, o = tid & 1;
            float s = b_out[o];
            const float* w = W_out + o * 128;
#pragma unroll 8
            for (int k = 0; k < 128; ++k)
                s += sh_hd[(128 + k) * 64 + 2 * b] * __ldg(&w[k]);
            out[(size_t)(base + b) * (SEQ * 2) + t * 2 + o] = s;
        }
        // head reads hd l1; next writes to hd l1 are >=3 syncs away. safe.
    }
}

extern "C" void kernel_launch(void* const* d_in, const int* in_sizes, int n_in,
                              void* d_out, int out_size) {
    const float* ff   = (const float*)d_in[0];   // fused_features [B,128]
    const float* ip   = (const float*)d_in[1];   // intent_prob    [B,1]
    const float* Wi   = (const float*)d_in[2];   // W_init  [512,129]
    const float* bi   = (const float*)d_in[3];   // b_init  [512]
    const float* W0   = (const float*)d_in[4];   // W_ih_l0 [512,129]
    const float* Wh0  = (const float*)d_in[5];   // W_hh_l0 [512,128]
    const float* bi0  = (const float*)d_in[6];
    const float* bh0  = (const float*)d_in[7];
    const float* W1i  = (const float*)d_in[8];   // W_ih_l1 [512,128]
    const float* W1h  = (const float*)d_in[9];   // W_hh_l1 [512,128]
    const float* bi1  = (const float*)d_in[10];
    const float* bh1  = (const float*)d_in[11];
    const float* Wout = (const float*)d_in[12];  // [2,128]
    const float* bout = (const float*)d_in[13];  // [2]
    (void)n_in; (void)out_size;

    int B = in_sizes[0] / 128;

    prep_kernel<<<128, 256>>>(Wi, W0, Wh0, W1i, W1h, bi0, bh0, bi1, bh1);

    cudaFuncSetAttribute(traj_kernel, cudaFuncAttributeMaxDynamicSharedMemorySize, SMEM_BYTES);
    traj_kernel<<<B / TB, NTHREADS, SMEM_BYTES>>>(ff, ip, bi, Wout, bout, (float*)d_out, B);
}

// round 7
// speedup vs baseline: 1.4449x; 1.0785x over previous
#include <cuda_runtime.h>
#include <cstdint>

#define SEQ 12
#define TB 32
#define NTHREADS 512
#define HSTRIDE 36   // sh_h row stride in floats (16B-aligned, conflict-mitigated)

// ---------------- gate-interleaved transposed weights: [K][128] float4 ----------------
// element (k, cg).gate = W[gate*128 + cg][k]
__device__ float4 g_WIg[132 * 128];   // W_init^T, K padded 132
__device__ float4 g_W0g[132 * 128];   // W_ih_l0^T, padded
__device__ float4 g_Wh0g[128 * 128];  // W_hh_l0^T
__device__ float4 g_W1g[256 * 128];   // [W_ih_l1 ; W_hh_l1]^T (K=256)
__device__ float4 g_b0g[128];         // (b_ih_l0+b_hh_l0) gate-interleaved
__device__ float4 g_b1g[128];         // (b_ih_l1+b_hh_l1)
__device__ float4 g_big[128];         // b_init

__global__ void prep_kernel(const float* __restrict__ Wi, const float* __restrict__ bIn,
                            const float* __restrict__ W0, const float* __restrict__ Wh0,
                            const float* __restrict__ W1i, const float* __restrict__ W1h,
                            const float* __restrict__ bi0, const float* __restrict__ bh0,
                            const float* __restrict__ bi1, const float* __restrict__ bh1) {
    int stride = gridDim.x * blockDim.x;
    int t0 = blockIdx.x * blockDim.x + threadIdx.x;
    float* WIg  = (float*)g_WIg;
    float* W0g  = (float*)g_W0g;
    float* Wh0g = (float*)g_Wh0g;
    float* W1g  = (float*)g_W1g;
    for (int i = t0; i < 132 * 512; i += stride) {
        int k = i >> 9, r = i & 511, cg = r >> 2, gate = r & 3;
        int j = gate * 128 + cg;
        WIg[i] = (k < 129) ? Wi[j * 129 + k] : 0.f;
        W0g[i] = (k < 129) ? W0[j * 129 + k] : 0.f;
    }
    for (int i = t0; i < 128 * 512; i += stride) {
        int k = i >> 9, r = i & 511, cg = r >> 2, gate = r & 3;
        int j = gate * 128 + cg;
        Wh0g[i] = Wh0[j * 128 + k];
    }
    for (int i = t0; i < 256 * 512; i += stride) {
        int k = i >> 9, r = i & 511, cg = r >> 2, gate = r & 3;
        int j = gate * 128 + cg;
        W1g[i] = (k < 128) ? W1i[j * 128 + k] : W1h[j * 128 + (k - 128)];
    }
    for (int i = t0; i < 512; i += stride) {
        int cg = i >> 2, gate = i & 3;
        int j = gate * 128 + cg;
        ((float*)g_b0g)[i] = bi0[j] + bh0[j];
        ((float*)g_b1g)[i] = bi1[j] + bh1[j];
        ((float*)g_big)[i] = bIn[j];
    }
}

// ---------------- packed f32x2 helpers ----------------
typedef unsigned long long u64;

__device__ __forceinline__ u64 pk2(float lo, float hi) {
    u64 r; asm("mov.b64 %0, {%1, %2};" : "=l"(r) : "f"(lo), "f"(hi)); return r;
}
__device__ __forceinline__ void upk2(u64 v, float& lo, float& hi) {
    asm("mov.b64 {%0, %1}, %2;" : "=f"(lo), "=f"(hi) : "l"(v));
}
__device__ __forceinline__ u64 dup2(float x) { return pk2(x, x); }
__device__ __forceinline__ void fma2(u64& d, u64 a, u64 b) {
    asm("fma.rn.f32x2 %0, %1, %2, %0;" : "+l"(d) : "l"(a), "l"(b));
}

__device__ __forceinline__ float sigm(float x) {
    return __fdividef(1.f, 1.f + __expf(-x));
}
__device__ __forceinline__ float tanh_(float x) {
    x = fmaxf(x, -44.f);
    float e = __expf(-2.f * x);
    return __fdividef(1.f - e, 1.f + e);
}

// GEMM micro-tile: thread owns 8 batches (4 packed pairs) x 4 gate-columns of unit cg.
// Per k: 1 LDG.128 (weights, gate-interleaved) + 2 broadcast LDS.128 (h pairs) + 16 FFMA2.
// acc[gate][pair]: pair p packs batches (2p, 2p+1) of the thread's octet.
template <int K, int RS>
__device__ __forceinline__ void gemmG(const float4* __restrict__ wt,
                                      const float* sa, int rowoff, int cg,
                                      u64 acc[4][4]) {
#pragma unroll 4
    for (int k = 0; k < K; ++k) {
        float4 w4 = __ldg(wt + k * 128 + cg);
        const float* a = sa + k * RS + rowoff;
        ulonglong2 p0 = *reinterpret_cast<const ulonglong2*>(a);      // batches 0..3
        ulonglong2 p1 = *reinterpret_cast<const ulonglong2*>(a + 4);  // batches 4..7
        u64 wi = dup2(w4.x), wf = dup2(w4.y), wg = dup2(w4.z), wo = dup2(w4.w);
        fma2(acc[0][0], p0.x, wi); fma2(acc[1][0], p0.x, wf);
        fma2(acc[2][0], p0.x, wg); fma2(acc[3][0], p0.x, wo);
        fma2(acc[0][1], p0.y, wi); fma2(acc[1][1], p0.y, wf);
        fma2(acc[2][1], p0.y, wg); fma2(acc[3][1], p0.y, wo);
        fma2(acc[0][2], p1.x, wi); fma2(acc[1][2], p1.x, wf);
        fma2(acc[2][2], p1.x, wg); fma2(acc[3][2], p1.x, wo);
        fma2(acc[0][3], p1.y, wi); fma2(acc[1][3], p1.y, wf);
        fma2(acc[2][3], p1.y, wg); fma2(acc[3][3], p1.y, wo);
    }
}

__device__ __forceinline__ void bias_fill(float4 b, u64 acc[4][4]) {
    u64 d0 = dup2(b.x), d1 = dup2(b.y), d2 = dup2(b.z), d3 = dup2(b.w);
#pragma unroll
    for (int p = 0; p < 4; ++p) {
        acc[0][p] = d0; acc[1][p] = d1; acc[2][p] = d2; acc[3][p] = d3;
    }
}

// register-resident LSTM elementwise update: c updated in place, h -> hn
__device__ __forceinline__ void ew(const u64 acc[4][4], float c[8], float hn[8]) {
#pragma unroll
    for (int p = 0; p < 4; ++p) {
        float i0, i1, f0, f1, g0, g1, o0, o1;
        upk2(acc[0][p], i0, i1); upk2(acc[1][p], f0, f1);
        upk2(acc[2][p], g0, g1); upk2(acc[3][p], o0, o1);
        float cn0 = sigm(f0) * c[2 * p]     + sigm(i0) * tanh_(g0);
        float cn1 = sigm(f1) * c[2 * p + 1] + sigm(i1) * tanh_(g1);
        c[2 * p] = cn0; c[2 * p + 1] = cn1;
        hn[2 * p]     = sigm(o0) * tanh_(cn0);
        hn[2 * p + 1] = sigm(o1) * tanh_(cn1);
    }
}

// smem: sh_h [256][HSTRIDE] | sh_x [132][64] | sh_i [32][516]
#define SH_H_FLOATS (256 * HSTRIDE)
#define SH_X_OFF    SH_H_FLOATS
#define SH_X_FLOATS (132 * 64)
#define SH_I_OFF    (SH_H_FLOATS + SH_X_FLOATS)
#define SH_I_FLOATS (32 * 516)
#define SMEM_FLOATS (SH_I_OFF + SH_I_FLOATS)
#define SMEM_BYTES  (SMEM_FLOATS * 4)

__global__ void __launch_bounds__(NTHREADS, 1)
traj_kernel(const float* __restrict__ ff, const float* __restrict__ ip,
            const float* __restrict__ W_out, const float* __restrict__ b_out,
            float* __restrict__ out, int B) {
    extern __shared__ float sm[];
    float* sh_h = sm;                 // [256][HSTRIDE] rows 0..127 = h1, 128..255 = h2
    float* sh_x = sm + SH_X_OFF;      // [132][64] (prologue only)
    float* sh_i = sm + SH_I_OFF;      // [32][516] init staging (prologue only)

    const int tid  = threadIdx.x;
    const int base = blockIdx.x * TB;
    const int bq   = tid >> 7;        // 0..3: batches 8bq..8bq+7
    const int cg   = tid & 127;       // 0..127: hidden unit / k index

    // ---- stage x: rows 0-31 tile batches, 32-47 l0-init rows, 48-63 l1-init rows ----
    for (int i = tid; i < 64 * 132; i += NTHREADS) {
        int row = i / 132, kk = i - row * 132;
        int gb;
        if (row < 32)      gb = base + row;
        else if (row < 48) gb = (base >> 1) + (row - 32);
        else               gb = (B >> 1) + (base >> 1) + (row - 48);
        float v = 0.f;
        if (kk < 128)       v = ff[(size_t)gb * 128 + kk];
        else if (kk == 128) v = ip[gb];
        sh_x[kk * 64 + row] = v;
    }
    __syncthreads();

    // ---- pre0 = x @ W_ih_l0^T + bsum0 (registers, reused all 12 steps) ----
    u64 pre0[4][4];
    bias_fill(__ldg(&g_b0g[cg]), pre0);
    gemmG<132, 64>(g_W0g, sh_x, 8 * bq, cg, pre0);

    // ---- init = x_init @ W_init^T + b_init -> staged to sh_i ----
    {
        u64 acc[4][4];
        bias_fill(__ldg(&g_big[cg]), acc);
        gemmG<132, 64>(g_WIg, sh_x, 32 + 8 * bq, cg, acc);
#pragma unroll
        for (int g = 0; g < 4; ++g)
#pragma unroll
            for (int p = 0; p < 4; ++p) {
                float v0, v1; upk2(acc[g][p], v0, v1);
                int j = g * 128 + cg;
                sh_i[(8 * bq + 2 * p) * 516 + j] = v0;
                sh_i[(8 * bq + 2 * p + 1) * 516 + j] = v1;
            }
    }
    __syncthreads();

    // ---- scatter init (torch reshape(2,B,H) shuffle): c -> regs, h -> sh_h ----
    float c1[8], c2[8];
#pragma unroll
    for (int bi = 0; bi < 8; ++bi) {
        int b = 8 * bq + bi;
        int r0 = b >> 1, par = b & 1;
        int jh = par * 128 + cg;
        c1[bi] = sh_i[r0 * 516 + 256 + jh];
        c2[bi] = sh_i[(16 + r0) * 516 + 256 + jh];
        sh_h[cg * HSTRIDE + b]         = sh_i[r0 * 516 + jh];
        sh_h[(128 + cg) * HSTRIDE + b] = sh_i[(16 + r0) * 516 + jh];
    }
    // hoist loop-invariant bias
    const float4 b1v = __ldg(&g_b1g[cg]);
    __syncthreads();

    // ---- main recurrence ----
    for (int t = 0; t < SEQ; ++t) {
        u64 acc[4][4];
        float hn[8];

        // GEMM0: gates = pre0 + h1 @ W_hh_l0^T   (K=128, reads sh_h rows 0..127)
#pragma unroll
        for (int g = 0; g < 4; ++g)
#pragma unroll
            for (int p = 0; p < 4; ++p) acc[g][p] = pre0[g][p];
        gemmG<128, HSTRIDE>(g_Wh0g, sh_h, 8 * bq, cg, acc);
        __syncthreads();                 // all reads of old h1 done

        ew(acc, c1, hn);                 // update c1 (regs), produce new h1
        {
            float4* d = reinterpret_cast<float4*>(&sh_h[cg * HSTRIDE + 8 * bq]);
            d[0] = make_float4(hn[0], hn[1], hn[2], hn[3]);
            d[1] = make_float4(hn[4], hn[5], hn[6], hn[7]);
        }
        __syncthreads();                 // new h1 visible

        // GEMM1: gates = bsum1 + [h1;h2] @ [W_ih_l1;W_hh_l1]^T (K=256, rows 0..255)
        bias_fill(b1v, acc);
        gemmG<256, HSTRIDE>(g_W1g, sh_h, 8 * bq, cg, acc);
        __syncthreads();                 // all reads of old h2 done

        ew(acc, c2, hn);                 // update c2 (regs), produce new h2
        {
            float4* d = reinterpret_cast<float4*>(&sh_h[(128 + cg) * HSTRIDE + 8 * bq]);
            d[0] = make_float4(hn[0], hn[1], hn[2], hn[3]);
            d[1] = make_float4(hn[4], hn[5], hn[6], hn[7]);
        }
        __syncthreads();                 // new h2 visible

        // output head: out[b, t, :] = h2 @ W_out^T + b_out (overlaps next GEMM0)
        if (tid < 64) {
            int b = tid >> 1, o = tid & 1;
            float s = b_out[o];
            const float* w = W_out + o * 128;
#pragma unroll 8
            for (int k = 0; k < 128; ++k)
                s += sh_h[(128 + k) * HSTRIDE + b] * __ldg(&w[k]);
            out[(size_t)(base + b) * (SEQ * 2) + t * 2 + o] = s;
        }
        // safe: next writes to sh_h (h1 rows) happen only after the next
        // iteration's __syncthreads, which head threads reach after finishing.
    }
}

extern "C" void kernel_launch(void* const* d_in, const int* in_sizes, int n_in,
                              void* d_out, int out_size) {
    const float* ff   = (const float*)d_in[0];   // fused_features [B,128]
    const float* ip   = (const float*)d_in[1];   // intent_prob    [B,1]
    const float* Wi   = (const float*)d_in[2];   // W_init  [512,129]
    const float* bi   = (const float*)d_in[3];   // b_init  [512]
    const float* W0   = (const float*)d_in[4];   // W_ih_l0 [512,129]
    const float* Wh0  = (const float*)d_in[5];   // W_hh_l0 [512,128]
    const float* bi0  = (const float*)d_in[6];
    const float* bh0  = (const float*)d_in[7];
    const float* W1i  = (const float*)d_in[8];   // W_ih_l1 [512,128]
    const float* W1h  = (const float*)d_in[9];   // W_hh_l1 [512,128]
    const float* bi1  = (const float*)d_in[10];
    const float* bh1  = (const float*)d_in[11];
    const float* Wout = (const float*)d_in[12];  // [2,128]
    const float* bout = (const float*)d_in[13];  // [2]
    (void)n_in; (void)out_size;

    int B = in_sizes[0] / 128;

    prep_kernel<<<128, 256>>>(Wi, bi, W0, Wh0, W1i, W1h, bi0, bh0, bi1, bh1);

    cudaFuncSetAttribute(traj_kernel, cudaFuncAttributeMaxDynamicSharedMemorySize, SMEM_BYTES);
    traj_kernel<<<B / TB, NTHREADS, SMEM_BYTES>>>(ff, ip, Wout, bout, (float*)d_out, B);
}

// round 11
// speedup vs baseline: 2.0006x; 1.3846x over previous
#include <cuda_runtime.h>
#include <cstdint>

#define SEQ 12
#define TB 32
#define NTHREADS 512
#define HSTRIDE 36
#define P0STRIDE 34
#define KPAD 136

// ---------------- gate-interleaved transposed weights: [K][128] float4 ----------------
// element (k, cg).gate = W[gate*128 + cg][k]
__device__ float4 g_WIg[KPAD * 128];   // W_init^T, K padded to 136
__device__ float4 g_W0g[KPAD * 128];   // W_ih_l0^T, padded
__device__ float4 g_Wh0g[128 * 128];   // W_hh_l0^T
__device__ float4 g_W1g[256 * 128];    // [W_ih_l1 ; W_hh_l1]^T (K=256)
__device__ float4 g_b0g[128];          // (b_ih_l0+b_hh_l0) gate-interleaved
__device__ float4 g_b1g[128];          // (b_ih_l1+b_hh_l1)
__device__ float4 g_big[128];          // b_init

__global__ void prep_kernel(const float* __restrict__ Wi, const float* __restrict__ bIn,
                            const float* __restrict__ W0, const float* __restrict__ Wh0,
                            const float* __restrict__ W1i, const float* __restrict__ W1h,
                            const float* __restrict__ bi0, const float* __restrict__ bh0,
                            const float* __restrict__ bi1, const float* __restrict__ bh1) {
    int stride = gridDim.x * blockDim.x;
    int t0 = blockIdx.x * blockDim.x + threadIdx.x;
    float* WIg  = (float*)g_WIg;
    float* W0g  = (float*)g_W0g;
    float* Wh0g = (float*)g_Wh0g;
    float* W1g  = (float*)g_W1g;
    for (int i = t0; i < KPAD * 512; i += stride) {
        int k = i >> 9, r = i & 511, cg = r >> 2, gate = r & 3;
        int j = gate * 128 + cg;
        WIg[i] = (k < 129) ? Wi[j * 129 + k] : 0.f;
        W0g[i] = (k < 129) ? W0[j * 129 + k] : 0.f;
    }
    for (int i = t0; i < 128 * 512; i += stride) {
        int k = i >> 9, r = i & 511, cg = r >> 2, gate = r & 3;
        int j = gate * 128 + cg;
        Wh0g[i] = Wh0[j * 128 + k];
    }
    for (int i = t0; i < 256 * 512; i += stride) {
        int k = i >> 9, r = i & 511, cg = r >> 2, gate = r & 3;
        int j = gate * 128 + cg;
        W1g[i] = (k < 128) ? W1i[j * 128 + k] : W1h[j * 128 + (k - 128)];
    }
    for (int i = t0; i < 512; i += stride) {
        int cg = i >> 2, gate = i & 3;
        int j = gate * 128 + cg;
        ((float*)g_b0g)[i] = bi0[j] + bh0[j];
        ((float*)g_b1g)[i] = bi1[j] + bh1[j];
        ((float*)g_big)[i] = bIn[j];
    }
}

// ---------------- packed f32x2 helpers ----------------
typedef unsigned long long u64;

__device__ __forceinline__ u64 pk2(float lo, float hi) {
    u64 r; asm("mov.b64 %0, {%1, %2};" : "=l"(r) : "f"(lo), "f"(hi)); return r;
}
__device__ __forceinline__ void upk2(u64 v, float& lo, float& hi) {
    asm("mov.b64 {%0, %1}, %2;" : "=f"(lo), "=f"(hi) : "l"(v));
}
__device__ __forceinline__ u64 dup2(float x) { return pk2(x, x); }
__device__ __forceinline__ void fma2(u64& d, u64 a, u64 b) {
    asm("fma.rn.f32x2 %0, %1, %2, %0;" : "+l"(d) : "l"(a), "l"(b));
}

__device__ __forceinline__ float sigm(float x) {
    return __fdividef(1.f, 1.f + __expf(-x));
}
__device__ __forceinline__ float tanh_(float x) {
    x = fmaxf(x, -44.f);
    float e = __expf(-2.f * x);
    return __fdividef(1.f - e, 1.f + e);
}

// one k-slice: 1 weight float4 (4 gates of unit cg) x 8 batches (4 packed pairs)
__device__ __forceinline__ void mtile(float4 w4, const float* a, u64 acc[4][4]) {
    ulonglong2 p0 = *reinterpret_cast<const ulonglong2*>(a);      // batches 0..3
    ulonglong2 p1 = *reinterpret_cast<const ulonglong2*>(a + 4);  // batches 4..7
    u64 wi = dup2(w4.x), wf = dup2(w4.y), wg = dup2(w4.z), wo = dup2(w4.w);
    fma2(acc[0][0], p0.x, wi); fma2(acc[1][0], p0.x, wf);
    fma2(acc[2][0], p0.x, wg); fma2(acc[3][0], p0.x, wo);
    fma2(acc[0][1], p0.y, wi); fma2(acc[1][1], p0.y, wf);
    fma2(acc[2][1], p0.y, wg); fma2(acc[3][1], p0.y, wo);
    fma2(acc[0][2], p1.x, wi); fma2(acc[1][2], p1.x, wf);
    fma2(acc[2][2], p1.x, wg); fma2(acc[3][2], p1.x, wo);
    fma2(acc[0][3], p1.y, wi); fma2(acc[1][3], p1.y, wf);
    fma2(acc[2][3], p1.y, wg); fma2(acc[3][3], p1.y, wo);
}

// GEMM with explicit double-buffered weight prefetch (8-k lookahead).
template <int K, int RS>
__device__ __forceinline__ void gemmG(const float4* __restrict__ wt,
                                      const float* sa, int rowoff, int cg,
                                      u64 acc[4][4]) {
    static_assert(K % 8 == 0, "K must be multiple of 8");
    const float4* wp = wt + cg;
    const float* a = sa + rowoff;
    float4 wa[4], wb[4];
#pragma unroll
    for (int i = 0; i < 4; ++i) wa[i] = __ldg(wp + i * 128);
#pragma unroll
    for (int i = 0; i < 4; ++i) wb[i] = __ldg(wp + (4 + i) * 128);
    for (int kb = 0; kb < K / 8 - 1; ++kb) {
#pragma unroll
        for (int i = 0; i < 4; ++i) mtile(wa[i], a + (8 * kb + i) * RS, acc);
#pragma unroll
        for (int i = 0; i < 4; ++i) wa[i] = __ldg(wp + (8 * kb + 8 + i) * 128);
#pragma unroll
        for (int i = 0; i < 4; ++i) mtile(wb[i], a + (8 * kb + 4 + i) * RS, acc);
#pragma unroll
        for (int i = 0; i < 4; ++i) wb[i] = __ldg(wp + (8 * kb + 12 + i) * 128);
    }
    {
        const int kb = K / 8 - 1;
#pragma unroll
        for (int i = 0; i < 4; ++i) mtile(wa[i], a + (8 * kb + i) * RS, acc);
#pragma unroll
        for (int i = 0; i < 4; ++i) mtile(wb[i], a + (8 * kb + 4 + i) * RS, acc);
    }
}

__device__ __forceinline__ void bias_fill(float4 b, u64 acc[4][4]) {
    u64 d0 = dup2(b.x), d1 = dup2(b.y), d2 = dup2(b.z), d3 = dup2(b.w);
#pragma unroll
    for (int p = 0; p < 4; ++p) {
        acc[0][p] = d0; acc[1][p] = d1; acc[2][p] = d2; acc[3][p] = d3;
    }
}

// register-resident LSTM elementwise update: c updated in place, h -> hn
__device__ __forceinline__ void ew(const u64 acc[4][4], float c[8], float hn[8]) {
#pragma unroll
    for (int p = 0; p < 4; ++p) {
        float i0, i1, f0, f1, g0, g1, o0, o1;
        upk2(acc[0][p], i0, i1); upk2(acc[1][p], f0, f1);
        upk2(acc[2][p], g0, g1); upk2(acc[3][p], o0, o1);
        float cn0 = sigm(f0) * c[2 * p]     + sigm(i0) * tanh_(g0);
        float cn1 = sigm(f1) * c[2 * p + 1] + sigm(i1) * tanh_(g1);
        c[2 * p] = cn0; c[2 * p + 1] = cn1;
        hn[2 * p]     = sigm(o0) * tanh_(cn0);
        hn[2 * p + 1] = sigm(o1) * tanh_(cn1);
    }
}

// smem layout (floats):
//   sh_h  : 2 buffers x [256][HSTRIDE]      (rows 0..127 = h1, 128..255 = h2)
//   sh_p0 : [512][P0STRIDE]                 (pre0, persists all steps)
//   scratch (prologue only): sh_x [KPAD][64] then sh_ci [2][128][32]
#define SH_H_FLOATS  (2 * 256 * HSTRIDE)
#define SH_P0_OFF    SH_H_FLOATS
#define SH_P0_FLOATS (512 * P0STRIDE)
#define SH_X_OFF     (SH_P0_OFF + SH_P0_FLOATS)
#define SH_X_FLOATS  (KPAD * 64)
#define SH_CI_OFF    (SH_X_OFF + SH_X_FLOATS)
#define SH_CI_FLOATS (2 * 128 * 32)
#define SMEM_FLOATS  (SH_CI_OFF + SH_CI_FLOATS)
#define SMEM_BYTES   (SMEM_FLOATS * 4)

__global__ void __launch_bounds__(NTHREADS, 1)
traj_kernel(const float* __restrict__ ff, const float* __restrict__ ip,
            const float* __restrict__ W_out, const float* __restrict__ b_out,
            float* __restrict__ out, int B) {
    extern __shared__ float sm[];
    float* sh_h  = sm;
    float* sh_p0 = sm + SH_P0_OFF;
    float* sh_x  = sm + SH_X_OFF;
    float* sh_ci = sm + SH_CI_OFF;

    const int tid  = threadIdx.x;
    const int base = blockIdx.x * TB;
    const int bq   = tid >> 7;        // 0..3: batches 8bq..8bq+7
    const int cg   = tid & 127;       // 0..127: hidden unit index

    // ---- stage x: rows 0-31 tile batches, 32-47 l0-init rows, 48-63 l1-init rows ----
    for (int i = tid; i < 64 * KPAD; i += NTHREADS) {
        int row = i / KPAD, kk = i - row * KPAD;
        int gb;
        if (row < 32)      gb = base + row;
        else if (row < 48) gb = (base >> 1) + (row - 32);
        else               gb = (B >> 1) + (base >> 1) + (row - 48);
        float v = 0.f;
        if (kk < 128)       v = ff[(size_t)gb * 128 + kk];
        else if (kk == 128) v = ip[gb];
        sh_x[kk * 64 + row] = v;
    }
    __syncthreads();

    // ---- pre0 = x @ W_ih_l0^T + bsum0 -> smem (persists all 12 steps) ----
    {
        u64 acc[4][4];
        bias_fill(__ldg(&g_b0g[cg]), acc);
        gemmG<KPAD, 64>(g_W0g, sh_x, 8 * bq, cg, acc);
#pragma unroll
        for (int g = 0; g < 4; ++g)
#pragma unroll
            for (int p = 0; p < 4; ++p)
                *reinterpret_cast<u64*>(
                    &sh_p0[(g * 128 + cg) * P0STRIDE + 8 * bq + 2 * p]) = acc[g][p];
    }

    // ---- init = x_init @ W_init^T + b_init; scatter per torch reshape(2,B,H) ----
    // thread's 4 gate-columns of unit cg map to: g0 -> h par0, g1 -> h par1,
    // g2 -> c par0, g3 -> c par1. init row rl: rl<16 -> layer0 (batches 2rl,2rl+1),
    // rl>=16 -> layer1.
    {
        u64 acc[4][4];
        bias_fill(__ldg(&g_big[cg]), acc);
        gemmG<KPAD, 64>(g_WIg, sh_x, 32 + 8 * bq, cg, acc);
#pragma unroll
        for (int p = 0; p < 4; ++p) {
            float hv[2][2], cv[2][2];             // [e][par]
            upk2(acc[0][p], hv[0][0], hv[1][0]);
            upk2(acc[1][p], hv[0][1], hv[1][1]);
            upk2(acc[2][p], cv[0][0], cv[1][0]);
            upk2(acc[3][p], cv[0][1], cv[1][1]);
#pragma unroll
            for (int e = 0; e < 2; ++e) {
                int rl = 8 * bq + 2 * p + e;
                int half = rl >> 4, ii = rl & 15;
                float* hrow = sh_h + (half * 128 + cg) * HSTRIDE;   // buffer 0
                hrow[2 * ii]     = hv[e][0];
                hrow[2 * ii + 1] = hv[e][1];
                float* crow = sh_ci + (half * 128 + cg) * 32;
                crow[2 * ii]     = cv[e][0];
                crow[2 * ii + 1] = cv[e][1];
            }
        }
    }
    const float4 b1v = __ldg(&g_b1g[cg]);
    __syncthreads();

    float c1[8], c2[8];
#pragma unroll
    for (int bi = 0; bi < 8; ++bi) {
        c1[bi] = sh_ci[cg * 32 + 8 * bq + bi];
        c2[bi] = sh_ci[(128 + cg) * 32 + 8 * bq + bi];
    }

    float* hcur = sh_h;                    // current-state buffer
    float* hnxt = sh_h + 256 * HSTRIDE;    // next-state buffer

    // ---- main recurrence: 2 syncs per step (double-buffered h) ----
    for (int t = 0; t < SEQ; ++t) {
        u64 acc[4][4];
        float hn[8];

        // GEMM0: gates = pre0 + h1(cur) @ W_hh_l0^T
#pragma unroll
        for (int g = 0; g < 4; ++g)
#pragma unroll
            for (int p = 0; p < 4; ++p)
                acc[g][p] = *reinterpret_cast<const u64*>(
                    &sh_p0[(g * 128 + cg) * P0STRIDE + 8 * bq + 2 * p]);
        gemmG<128, HSTRIDE>(g_Wh0g, hcur, 8 * bq, cg, acc);

        ew(acc, c1, hn);                   // new h1 -> NEXT buffer (no WAR hazard)
        {
            float4* d = reinterpret_cast<float4*>(&hnxt[cg * HSTRIDE + 8 * bq]);
            d[0] = make_float4(hn[0], hn[1], hn[2], hn[3]);
            d[1] = make_float4(hn[4], hn[5], hn[6], hn[7]);
        }
        __syncthreads();                   // h1(nxt) visible

        // GEMM1: gates = bsum1 + h1(nxt) @ W_ih_l1^T + h2(cur) @ W_hh_l1^T
        bias_fill(b1v, acc);
        gemmG<128, HSTRIDE>(g_W1g, hnxt, 8 * bq, cg, acc);
        gemmG<128, HSTRIDE>(g_W1g + 128 * 128, hcur + 128 * HSTRIDE, 8 * bq, cg, acc);

        ew(acc, c2, hn);                   // new h2 -> NEXT buffer
        {
            float4* d = reinterpret_cast<float4*>(&hnxt[(128 + cg) * HSTRIDE + 8 * bq]);
            d[0] = make_float4(hn[0], hn[1], hn[2], hn[3]);
            d[1] = make_float4(hn[4], hn[5], hn[6], hn[7]);
        }
        __syncthreads();                   // h2(nxt) visible

        // output head: out[b, t, :] = h2(nxt) @ W_out^T + b_out (overlaps next GEMM0)
        if (tid < 64) {
            int b = tid >> 1, o = tid & 1;
            float s = b_out[o];
            const float* w = W_out + o * 128;
            const float* h2r = hnxt + 128 * HSTRIDE + b;
#pragma unroll 8
            for (int k = 0; k < 128; ++k)
                s += h2r[k * HSTRIDE] * __ldg(&w[k]);
            out[(size_t)(base + b) * (SEQ * 2) + t * 2 + o] = s;
        }

        float* tmp = hcur; hcur = hnxt; hnxt = tmp;
    }
}

extern "C" void kernel_launch(void* const* d_in, const int* in_sizes, int n_in,
                              void* d_out, int out_size) {
    const float* ff   = (const float*)d_in[0];   // fused_features [B,128]
    const float* ip   = (const float*)d_in[1];   // intent_prob    [B,1]
    const float* Wi   = (const float*)d_in[2];   // W_init  [512,129]
    const float* bi   = (const float*)d_in[3];   // b_init  [512]
    const float* W0   = (const float*)d_in[4];   // W_ih_l0 [512,129]
    const float* Wh0  = (const float*)d_in[5];   // W_hh_l0 [512,128]
    const float* bi0  = (const float*)d_in[6];
    const float* bh0  = (const float*)d_in[7];
    const float* W1i  = (const float*)d_in[8];   // W_ih_l1 [512,128]
    const float* W1h  = (const float*)d_in[9];   // W_hh_l1 [512,128]
    const float* bi1  = (const float*)d_in[10];
    const float* bh1  = (const float*)d_in[11];
    const float* Wout = (const float*)d_in[12];  // [2,128]
    const float* bout = (const float*)d_in[13];  // [2]
    (void)n_in; (void)out_size;

    int B = in_sizes[0] / 128;

    prep_kernel<<<128, 256>>>(Wi, bi, W0, Wh0, W1i, W1h, bi0, bh0, bi1, bh1);

    cudaFuncSetAttribute(traj_kernel, cudaFuncAttributeMaxDynamicSharedMemorySize, SMEM_BYTES);
    traj_kernel<<<B / TB, NTHREADS, SMEM_BYTES>>>(ff, ip, Wout, bout, (float*)d_out, B);
}